// round 7
// baseline (speedup 1.0000x reference)
#include <cuda_runtime.h>
#include <cuda_bf16.h>
#include <cstdint>
#include <cstddef>

#define DIM       128
#define ROWS_CTA  128
#define THREADS   512
#define KSEL      32
#define APITCH    136                       // bf16 elems per row (272 B, 16B-aligned)
#define AIMG      (128*APITCH*2)            // 34816 B per split image
#define A_OFF     0
#define B_OFF     (3*AIMG)                  // 104448
#define STAGE_OFF (6*AIMG)                  // 208896
#define CAND_OFF  (STAGE_OFF + 16*4*KSEL*8) // 225280
#define SMEM_TOTAL (CAND_OFF + 16*64*4)     // 229376
#define YPITCH    132                       // fp32 y tile pitch (reuses A region)
#define TAU       1e-4f                     // ambiguity threshold (dot units)

__device__ float g_inv_len;
__device__ __align__(16) unsigned char g_vimg[3][AIMG];

// ---------------------------------------------------------------------------
// helpers
// ---------------------------------------------------------------------------
__device__ __forceinline__ uint32_t smem_u32(const void* p) {
    uint32_t a;
    asm("{ .reg .u64 t; cvta.to.shared.u64 t, %1; cvt.u32.u64 %0, t; }"
        : "=r"(a) : "l"(p));
    return a;
}
__device__ __forceinline__ uint32_t pack_bf2(float lo, float hi) {
    uint32_t r;
    asm("cvt.rn.bf16x2.f32 %0, %1, %2;" : "=r"(r) : "f"(hi), "f"(lo));
    return r;
}
__device__ __forceinline__ unsigned fkey(float f) {
    unsigned u = __float_as_uint(f);
    return (u & 0x80000000u) ? ~u : (u | 0x80000000u);
}
__device__ __forceinline__ float unfkey(unsigned m) {
    unsigned u = (m & 0x80000000u) ? (m & 0x7fffffffu) : ~m;
    return __uint_as_float(u);
}
#define CSWAP(ka, ca, kb, cb)                                   \
    {                                                           \
        bool sw = (ka < kb) || (ka == kb && ca > cb);           \
        unsigned tk_ = sw ? kb : ka;                            \
        unsigned tc_ = sw ? cb : ca;                            \
        kb = sw ? ka : kb;  cb = sw ? ca : cb;                  \
        ka = tk_;           ca = tc_;                           \
    }

__device__ __forceinline__ void ldm_x4(uint32_t addr, uint32_t* r) {
    asm volatile("ldmatrix.sync.aligned.m8n8.x4.shared.b16 {%0,%1,%2,%3}, [%4];"
                 : "=r"(r[0]), "=r"(r[1]), "=r"(r[2]), "=r"(r[3]) : "r"(addr));
}
__device__ __forceinline__ void mma_bf16(float* c, const uint32_t* a,
                                         uint32_t b0, uint32_t b1) {
    asm volatile(
        "mma.sync.aligned.m16n8k16.row.col.f32.bf16.bf16.f32 "
        "{%0,%1,%2,%3}, {%4,%5,%6,%7}, {%8,%9}, {%0,%1,%2,%3};"
        : "+f"(c[0]), "+f"(c[1]), "+f"(c[2]), "+f"(c[3])
        : "r"(a[0]), "r"(a[1]), "r"(a[2]), "r"(a[3]), "r"(b0), "r"(b1));
}

// ---------------------------------------------------------------------------
// prep: 1/||v|| and bf16 3-split images of B[n][k] = v[k][n], pitch APITCH
// ---------------------------------------------------------------------------
__global__ void prep_kernel(const float* __restrict__ v) {
    __shared__ float red[8];
    const int tid = threadIdx.x;
    float s = 0.f;
    for (int i = tid; i < DIM * DIM; i += 256) { float a = v[i]; s = fmaf(a, a, s); }
    #pragma unroll
    for (int o = 16; o; o >>= 1) s += __shfl_xor_sync(0xffffffffu, s, o);
    if ((tid & 31) == 0) red[tid >> 5] = s;
    __syncthreads();
    if (tid == 0) {
        float t = 0.f;
        #pragma unroll
        for (int i = 0; i < 8; i++) t += red[i];
        g_inv_len = 1.0f / sqrtf(t);
    }
    for (int i = tid; i < DIM * DIM; i += 256) {
        int k = i >> 7, n = i & 127;
        float a  = v[i];
        __nv_bfloat16 b0 = __float2bfloat16(a);
        float r1 = a - __bfloat162float(b0);
        __nv_bfloat16 b1 = __float2bfloat16(r1);
        float r2 = r1 - __bfloat162float(b1);
        uint32_t off = (uint32_t)(n * APITCH + k) * 2;
        *(__nv_bfloat16*)(g_vimg[0] + off) = b0;
        *(__nv_bfloat16*)(g_vimg[1] + off) = b1;
        *(__nv_bfloat16*)(g_vimg[2] + off) = __float2bfloat16(r2);
    }
}

// ---------------------------------------------------------------------------
// rare-path fixup: exact (reference-bit-identical) re-rank of ambiguous rows
// ---------------------------------------------------------------------------
__device__ __noinline__ void fixup_row(const float* __restrict__ x,
                                       const float* __restrict__ vfp,
                                       int grow, const float* __restrict__ ysh_row,
                                       uint2* st_row, int* candbuf, float y31) {
    const int lane = threadIdx.x & 31;
    const int col0 = (31 - lane) * 4;
    const float yt = y31 - TAU;

    // gather candidate columns: all c with approx y >= y31 - tau
    int base = 0;
    #pragma unroll
    for (int q = 0; q < 4; ++q) {
        int c = col0 + q;
        bool sel = (ysh_row[c] >= yt);
        unsigned bal = __ballot_sync(0xffffffffu, sel);
        int pos = base + __popc(bal & ((1u << lane) - 1u));
        if (sel && pos < 64) candbuf[pos] = c;
        base += __popc(bal);
    }
    int ncand = base < 64 ? base : 64;
    __syncwarp();

    // exact dots: ascending-k sequential fp32 fma (bit-identical to reference)
    int c1 = (lane < ncand) ? candbuf[lane] : -1;
    int c2 = (lane + 32 < ncand) ? candbuf[lane + 32] : -1;
    const float* xr = x + (size_t)grow * DIM;
    const float* v1 = vfp + ((c1 >= 0) ? c1 : 0);
    const float* v2 = vfp + ((c2 >= 0) ? c2 : 0);
    float a1 = 0.f, a2 = 0.f;
    #pragma unroll 4
    for (int k = 0; k < DIM; ++k) {
        float xv = __ldg(xr + k);
        a1 = fmaf(xv, __ldg(v1 + (size_t)k * DIM), a1);
        a2 = fmaf(xv, __ldg(v2 + (size_t)k * DIM), a2);
    }

    unsigned hk = (c1 >= 0) ? fkey(a1) : 0u;
    unsigned hc = (c1 >= 0) ? (unsigned)c1 : 0x7fffffffu;
    unsigned tk = (c2 >= 0) ? fkey(a2) : 0u;
    unsigned tc = (c2 >= 0) ? (unsigned)c2 : 0x7fffffffu;
    CSWAP(hk, hc, tk, tc);

    #pragma unroll 1
    for (int i = 0; i < KSEL; ++i) {
        unsigned m = __reduce_max_sync(0xffffffffu, hk);
        bool sel = (hk == m);
        unsigned colx = sel ? hc : 0x7fffffffu;
        unsigned minc = __reduce_min_sync(0xffffffffu, colx);   // jax tie-break
        bool win = sel && (hc == minc);
        if (win) st_row[i] = make_uint2(hc, hk);
        hk = win ? tk : hk;  hc = win ? tc : hc;  tk = win ? 0u : tk;
    }
    __syncwarp();
}

// ---------------------------------------------------------------------------
// main fused kernel: split -> HMMA (6 products) -> y SMEM -> top-32 -> out
// ---------------------------------------------------------------------------
__global__ __launch_bounds__(THREADS, 1)
void pool_kernel(const float* __restrict__ x, const float* __restrict__ vfp,
                 float* __restrict__ out, int nrows) {
    extern __shared__ __align__(16) char smem_c[];
    const uint32_t smem_base = smem_u32(smem_c);
    const int tid  = threadIdx.x;
    const int warp = tid >> 5, lane = tid & 31;
    const int row0 = blockIdx.x * ROWS_CTA;

    // ---- copy v split images (linear, layout-identical) ----
    {
        const float4* vg = (const float4*)g_vimg;
        float4* vs = (float4*)(smem_c + B_OFF);
        for (int i = tid; i < 3 * AIMG / 16; i += THREADS) vs[i] = vg[i];
    }

    // ---- load x tile, 3-way rn-bf16 split, store A images ----
    for (int i = tid; i < ROWS_CTA * DIM / 4; i += THREADS) {
        int row = i >> 5;
        int k4  = (i & 31) << 2;
        int grow = row0 + row;
        float4 a = make_float4(0.f, 0.f, 0.f, 0.f);
        if (grow < nrows) a = *(const float4*)(x + (size_t)grow * DIM + k4);

        uint32_t p0xy = pack_bf2(a.x, a.y);
        uint32_t p0zw = pack_bf2(a.z, a.w);
        float x0 = __uint_as_float(p0xy << 16), y0 = __uint_as_float(p0xy & 0xFFFF0000u);
        float z0 = __uint_as_float(p0zw << 16), w0 = __uint_as_float(p0zw & 0xFFFF0000u);
        float r1x = a.x - x0, r1y = a.y - y0, r1z = a.z - z0, r1w = a.w - w0;
        uint32_t p1xy = pack_bf2(r1x, r1y);
        uint32_t p1zw = pack_bf2(r1z, r1w);
        float x1 = __uint_as_float(p1xy << 16), y1 = __uint_as_float(p1xy & 0xFFFF0000u);
        float z1 = __uint_as_float(p1zw << 16), w1 = __uint_as_float(p1zw & 0xFFFF0000u);
        uint32_t p2xy = pack_bf2(r1x - x1, r1y - y1);
        uint32_t p2zw = pack_bf2(r1z - z1, r1w - w1);

        uint32_t off = (uint32_t)(row * APITCH + k4) * 2;
        *(uint2*)(smem_c + A_OFF + 0 * AIMG + off) = make_uint2(p0xy, p0zw);
        *(uint2*)(smem_c + A_OFF + 1 * AIMG + off) = make_uint2(p1xy, p1zw);
        *(uint2*)(smem_c + A_OFF + 2 * AIMG + off) = make_uint2(p2xy, p2zw);
    }
    __syncthreads();

    // ---- HMMA: warp -> 16 rows x 64 cols; 6 split products accumulated ----
    const int mw = warp & 7, nh = warp >> 3;
    const int wr0 = mw * 16;
    const int n_base = nh * 64;
    const int g = lane >> 3, lr = lane & 7;
    const uint32_t a_addr = smem_base + A_OFF +
        (uint32_t)((wr0 + lr + (g & 1) * 8) * APITCH + (g >> 1) * 8) * 2;
    const uint32_t b_addr = smem_base + B_OFF +
        (uint32_t)((n_base + lr + (g >> 1) * 8) * APITCH + (g & 1) * 8) * 2;

    float C[8][4];
    #pragma unroll
    for (int i = 0; i < 8; i++)
        #pragma unroll
        for (int j = 0; j < 4; j++) C[i][j] = 0.f;

    #pragma unroll
    for (int k = 0; k < 8; ++k) {
        uint32_t A[3][4];
        #pragma unroll
        for (int im = 0; im < 3; ++im)
            ldm_x4(a_addr + im * AIMG + k * 32, A[im]);
        #pragma unroll
        for (int ntp = 0; ntp < 4; ++ntp) {
            uint32_t B[3][4];
            #pragma unroll
            for (int im = 0; im < 3; ++im)
                ldm_x4(b_addr + im * AIMG + ntp * (16 * APITCH * 2) + k * 32, B[im]);
            float* c0 = C[2 * ntp];
            float* c1 = C[2 * ntp + 1];
            mma_bf16(c0, A[0], B[0][0], B[0][1]); mma_bf16(c1, A[0], B[0][2], B[0][3]);
            mma_bf16(c0, A[0], B[1][0], B[1][1]); mma_bf16(c1, A[0], B[1][2], B[1][3]);
            mma_bf16(c0, A[1], B[0][0], B[0][1]); mma_bf16(c1, A[1], B[0][2], B[0][3]);
            mma_bf16(c0, A[1], B[1][0], B[1][1]); mma_bf16(c1, A[1], B[1][2], B[1][3]);
            mma_bf16(c0, A[0], B[2][0], B[2][1]); mma_bf16(c1, A[0], B[2][2], B[2][3]);
            mma_bf16(c0, A[2], B[0][0], B[0][1]); mma_bf16(c1, A[2], B[0][2], B[0][3]);
        }
    }
    __syncthreads();     // A/B images dead; reuse A region for y

    // ---- write y fragments to SMEM ----
    float* ysh = (float*)(smem_c + A_OFF);
    {
        const int r = lane >> 2, q = lane & 3;
        #pragma unroll
        for (int nt = 0; nt < 8; ++nt) {
            int col = n_base + nt * 8 + 2 * q;
            *(float2*)(ysh + (wr0 + r) * YPITCH + col)     = make_float2(C[nt][0], C[nt][1]);
            *(float2*)(ysh + (wr0 + 8 + r) * YPITCH + col) = make_float2(C[nt][2], C[nt][3]);
        }
    }
    __syncthreads();

    // ---- selection: warp -> 8 rows, 4-row interleave, jax tie-break ----
    const float inv_len = g_inv_len;
    const int r0 = warp * 8;
    const int col0 = (31 - lane) * 4;           // FLO(ballot) -> lowest column
    uint2* st = (uint2*)(smem_c + STAGE_OFF) + warp * 4 * KSEL;
    int* candw = (int*)(smem_c + CAND_OFF) + warp * 64;

    #pragma unroll 1
    for (int pass = 0; pass < 2; ++pass) {
        unsigned kk[4][4], cc[4][4];
        #pragma unroll
        for (int j = 0; j < 4; ++j) {
            int row = r0 + pass * 4 + j;
            float4 y4 = *(const float4*)(ysh + row * YPITCH + col0);
            kk[j][0] = fkey(y4.x); kk[j][1] = fkey(y4.y);
            kk[j][2] = fkey(y4.z); kk[j][3] = fkey(y4.w);
            cc[j][0] = col0 + 0; cc[j][1] = col0 + 1;
            cc[j][2] = col0 + 2; cc[j][3] = col0 + 3;
            CSWAP(kk[j][0], cc[j][0], kk[j][1], cc[j][1]);
            CSWAP(kk[j][2], cc[j][2], kk[j][3], cc[j][3]);
            CSWAP(kk[j][0], cc[j][0], kk[j][2], cc[j][2]);
            CSWAP(kk[j][1], cc[j][1], kk[j][3], cc[j][3]);
            CSWAP(kk[j][1], cc[j][1], kk[j][2], cc[j][2]);
        }

        #pragma unroll 4
        for (int i = 0; i < KSEL; ++i) {
            #pragma unroll
            for (int j = 0; j < 4; ++j) {
                unsigned m   = __reduce_max_sync(0xffffffffu, kk[j][0]);
                unsigned bal = __ballot_sync(0xffffffffu, kk[j][0] == m);
                bool win = (lane == 31 - __clz(bal));
                if (win) st[j * KSEL + i] = make_uint2(cc[j][0], kk[j][0]);
                kk[j][0] = win ? kk[j][1] : kk[j][0];  cc[j][0] = win ? cc[j][1] : cc[j][0];
                kk[j][1] = win ? kk[j][2] : kk[j][1];  cc[j][1] = win ? cc[j][2] : cc[j][1];
                kk[j][2] = win ? kk[j][3] : kk[j][2];  cc[j][2] = win ? cc[j][3] : cc[j][2];
                kk[j][3] = win ? 0u       : kk[j][3];
            }
        }
        __syncwarp();

        // ---- gap check, rare fixup, output ----
        #pragma unroll
        for (int j = 0; j < 4; ++j) {
            const int rowl = r0 + pass * 4 + j;
            const int grow = row0 + rowl;
            if (grow < nrows) {
                uint2 p = st[j * KSEL + lane];
                float yl = unfkey(p.y);
                // 33rd-best approx value = max of remaining heap heads
                float y33 = unfkey(__reduce_max_sync(0xffffffffu, kk[j][0]));
                float ynext = __shfl_down_sync(0xffffffffu, yl, 1);
                if (lane == 31) ynext = y33;
                if (__ballot_sync(0xffffffffu, (yl - ynext) < TAU)) {
                    float y31 = __shfl_sync(0xffffffffu, yl, 31);
                    fixup_row(x, vfp, grow, ysh + rowl * YPITCH,
                              st + j * KSEL, candw, y31);
                    p = st[j * KSEL + lane];
                }
                float d  = unfkey(p.y) * inv_len;
                float sg = 1.0f / (1.0f + __expf(-d));
                float xv = __ldg(&x[(size_t)grow * DIM + p.x]);
                out[(size_t)grow * KSEL + lane] = xv * sg;
            }
            __syncwarp();
        }
    }
}

// ---------------------------------------------------------------------------
extern "C" void kernel_launch(void* const* d_in, const int* in_sizes, int n_in,
                              void* d_out, int out_size) {
    const float* x = (const float*)d_in[0];
    const float* v = (const float*)d_in[1];
    float* out = (float*)d_out;
    const int nrows = in_sizes[0] / DIM;

    cudaFuncSetAttribute(pool_kernel,
                         cudaFuncAttributeMaxDynamicSharedMemorySize, SMEM_TOTAL);

    prep_kernel<<<1, 256>>>(v);
    const int grid = (nrows + ROWS_CTA - 1) / ROWS_CTA;
    pool_kernel<<<grid, THREADS, SMEM_TOTAL>>>(x, v, out, nrows);
}